// round 2
// baseline (speedup 1.0000x reference)
#include <cuda_runtime.h>
#include <math.h>

// Problem constants
#define BB 8
#define SS 2048
#define DD 1024
#define MTOT (BB * SS)   // 16384

// Scratch (device globals; no allocation allowed)
__device__ float g_q[(size_t)MTOT * DD];
__device__ float g_k[(size_t)MTOT * DD];
__device__ float g_v[(size_t)MTOT * DD];
__device__ float g_s[(size_t)BB * SS * SS];
__device__ float g_x[(size_t)MTOT * DD];

// Packed fp32x2 FMA (Blackwell sm_103a FFMA2) — only reachable via PTX.
#define FMA_F32X2(d, a, b, c) \
    asm("fma.rn.f32x2 %0, %1, %2, %3;" : "=l"(d) : "l"(a), "l"(b), "l"(c))
#define PACK_DUP_F32X2(out, x) \
    asm("mov.b64 %0, {%1, %1};" : "=l"(out) : "r"(__float_as_uint(x)))

// ---------------------------------------------------------------------------
// Tiled SGEMM with packed f32x2 accumulation:
//   C[m,n] = alpha * sum_k A[m,k] * B'[k,n]  (+ bias[n])
//   BT=true : B is N x K row-major (B'[k,n] = B[n,k])  -- "NT" (proj, Q K^T)
//   BT=false: B is K x N row-major                     -- "NN" (P V)
// BM=BN=128, BK=16, 256 threads, 8x8 per-thread microtile (packed as 8x4 f32x2).
// ---------------------------------------------------------------------------
template <bool BT, bool BIAS>
__global__ __launch_bounds__(256, 2)
void sgemm_kernel(const float* __restrict__ A,
                  const float* __restrict__ B,
                  const float* __restrict__ bias,
                  float* __restrict__ C,
                  int M, int N, int K, float alpha,
                  long sA, long sB, long sC)
{
    constexpr int BM = 128, BN = 128, BK = 16;
    __shared__ float As[BK][BM + 4];   // +4 pad keeps 16B alignment, breaks conflicts
    __shared__ float Bs[BK][BN + 4];

    const int tid = threadIdx.x;
    const int tx = tid & 15;        // 0..15 -> n
    const int ty = tid >> 4;        // 0..15 -> m
    const int bm = blockIdx.x * BM;
    const int bn = blockIdx.y * BN;

    A += (long)blockIdx.z * sA;
    B += (long)blockIdx.z * sB;
    C += (long)blockIdx.z * sC;

    // 8x8 fp32 microtile packed as 8 x 4 f32x2 (pairs along n)
    unsigned long long acc2[8][4];
#pragma unroll
    for (int i = 0; i < 8; i++)
#pragma unroll
        for (int j = 0; j < 4; j++) acc2[i][j] = 0ULL;

    for (int k0 = 0; k0 < K; k0 += BK) {
        // ---- load A tile (BM x BK), transpose into As[k][m] ----
#pragma unroll
        for (int it = 0; it < 2; it++) {          // 512 float4 / 256 thr
            int idx = tid + it * 256;
            int r = idx >> 2, c4 = idx & 3;
            float4 v4 = *(const float4*)(A + (long)(bm + r) * K + k0 + c4 * 4);
            As[c4 * 4 + 0][r] = v4.x;
            As[c4 * 4 + 1][r] = v4.y;
            As[c4 * 4 + 2][r] = v4.z;
            As[c4 * 4 + 3][r] = v4.w;
        }
        // ---- load B tile ----
        if (BT) {
            // B rows bn..bn+BN, cols k0..k0+BK -> Bs[k][n]
#pragma unroll
            for (int it = 0; it < 2; it++) {
                int idx = tid + it * 256;
                int r = idx >> 2, c4 = idx & 3;
                float4 v4 = *(const float4*)(B + (long)(bn + r) * K + k0 + c4 * 4);
                Bs[c4 * 4 + 0][r] = v4.x;
                Bs[c4 * 4 + 1][r] = v4.y;
                Bs[c4 * 4 + 2][r] = v4.z;
                Bs[c4 * 4 + 3][r] = v4.w;
            }
        } else {
            // B rows k0..k0+BK, cols bn..bn+BN (contiguous along n)
#pragma unroll
            for (int it = 0; it < 2; it++) {
                int idx = tid + it * 256;
                int r = idx >> 5;           // /32 float4 per row
                int c4 = idx & 31;
                float4 v4 = *(const float4*)(B + (long)(k0 + r) * N + bn + c4 * 4);
                *(float4*)&Bs[r][c4 * 4] = v4;   // row stride 132*4=528B, 16B-aligned
            }
        }
        __syncthreads();

        // ---- compute (packed f32x2) ----
#pragma unroll
        for (int kk = 0; kk < BK; kk++) {
            // b pairs: 8 floats = 4 f32x2, 16B-aligned (tx*8 floats = 32B offset)
            unsigned long long bb[4];
            const unsigned long long* bp =
                (const unsigned long long*)&Bs[kk][tx * 8];
            bb[0] = bp[0]; bb[1] = bp[1]; bb[2] = bp[2]; bb[3] = bp[3];

            unsigned long long aa[8];
#pragma unroll
            for (int i = 0; i < 8; i++) {
                float av = As[kk][ty * 8 + i];
                PACK_DUP_F32X2(aa[i], av);
            }
#pragma unroll
            for (int i = 0; i < 8; i++)
#pragma unroll
                for (int j = 0; j < 4; j++)
                    FMA_F32X2(acc2[i][j], aa[i], bb[j], acc2[i][j]);
        }
        __syncthreads();
    }

    // ---- epilogue ----
#pragma unroll
    for (int i = 0; i < 8; i++) {
        int row = bm + ty * 8 + i;
#pragma unroll
        for (int j = 0; j < 8; j += 4) {
            int col = bn + tx * 8 + j;
            unsigned long long p0 = acc2[i][j / 2];
            unsigned long long p1 = acc2[i][j / 2 + 1];
            float4 v4;
            v4.x = __uint_as_float((unsigned)p0) * alpha;
            v4.y = __uint_as_float((unsigned)(p0 >> 32)) * alpha;
            v4.z = __uint_as_float((unsigned)p1) * alpha;
            v4.w = __uint_as_float((unsigned)(p1 >> 32)) * alpha;
            if (BIAS) {
                v4.x += bias[col + 0];
                v4.y += bias[col + 1];
                v4.z += bias[col + 2];
                v4.w += bias[col + 3];
            }
            *(float4*)(C + (long)row * N + col) = v4;
        }
    }
}

// ---------------------------------------------------------------------------
// Row softmax over rows of length SS. One block (256 thr) per row.
// ---------------------------------------------------------------------------
__global__ __launch_bounds__(256)
void softmax_rows(float* __restrict__ s)
{
    float* p = s + (long)blockIdx.x * SS;
    const int tid = threadIdx.x;
    __shared__ float red[256];

    float local[8];
    float mx = -1e30f;
#pragma unroll
    for (int i = 0; i < 8; i++) {
        local[i] = p[tid + i * 256];
        mx = fmaxf(mx, local[i]);
    }
    red[tid] = mx;
    __syncthreads();
#pragma unroll
    for (int o = 128; o > 0; o >>= 1) {
        if (tid < o) red[tid] = fmaxf(red[tid], red[tid + o]);
        __syncthreads();
    }
    mx = red[0];
    __syncthreads();

    float sum = 0.f;
#pragma unroll
    for (int i = 0; i < 8; i++) {
        local[i] = __expf(local[i] - mx);
        sum += local[i];
    }
    red[tid] = sum;
    __syncthreads();
#pragma unroll
    for (int o = 128; o > 0; o >>= 1) {
        if (tid < o) red[tid] += red[tid + o];
        __syncthreads();
    }
    float inv = 1.f / red[0];
#pragma unroll
    for (int i = 0; i < 8; i++)
        p[tid + i * 256] = local[i] * inv;
}

// ---------------------------------------------------------------------------
extern "C" void kernel_launch(void* const* d_in, const int* in_sizes, int n_in,
                              void* d_out, int out_size)
{
    const float* query = (const float*)d_in[0];
    const float* key   = (const float*)d_in[1];
    const float* value = (const float*)d_in[2];
    const float* Wq = (const float*)d_in[3];
    const float* bq = (const float*)d_in[4];
    const float* Wk = (const float*)d_in[5];
    const float* bk = (const float*)d_in[6];
    const float* Wv = (const float*)d_in[7];
    const float* bv = (const float*)d_in[8];
    const float* Wo = (const float*)d_in[9];
    const float* bo = (const float*)d_in[10];
    float* out = (float*)d_out;

    float *q, *k, *v, *s, *x;
    cudaGetSymbolAddress((void**)&q, g_q);
    cudaGetSymbolAddress((void**)&k, g_k);
    cudaGetSymbolAddress((void**)&v, g_v);
    cudaGetSymbolAddress((void**)&s, g_s);
    cudaGetSymbolAddress((void**)&x, g_x);

    const dim3 blk(256);

    // Projections: [16384,1024] = X[16384,1024] @ W^T + b  (NT, bias)
    dim3 gp(MTOT / 128, DD / 128, 1);
    sgemm_kernel<true, true><<<gp, blk>>>(query, Wq, bq, q, MTOT, DD, DD, 1.f, 0, 0, 0);
    sgemm_kernel<true, true><<<gp, blk>>>(key,   Wk, bk, k, MTOT, DD, DD, 1.f, 0, 0, 0);
    sgemm_kernel<true, true><<<gp, blk>>>(value, Wv, bv, v, MTOT, DD, DD, 1.f, 0, 0, 0);

    // Scores: per batch, S = (Q K^T) / sqrt(128)   (NT, batched)
    const float alpha = 0.088388347648318447f;   // 1/sqrt(128)
    dim3 gs(SS / 128, SS / 128, BB);
    sgemm_kernel<true, false><<<gs, blk>>>(q, k, nullptr, s, SS, SS, DD, alpha,
                                           (long)SS * DD, (long)SS * DD, (long)SS * SS);

    // Softmax over rows
    softmax_rows<<<BB * SS, blk>>>(s);

    // X = P V  (NN, batched)
    dim3 gx(SS / 128, DD / 128, BB);
    sgemm_kernel<false, false><<<gx, blk>>>(s, v, nullptr, x, SS, DD, SS, 1.f,
                                            (long)SS * SS, (long)SS * DD, (long)SS * DD);

    // Output projection -> d_out
    sgemm_kernel<true, true><<<gp, blk>>>(x, Wo, bo, out, MTOT, DD, DD, 1.f, 0, 0, 0);
}

// round 4
// speedup vs baseline: 2.5629x; 2.5629x over previous
#include <cuda_runtime.h>
#include <cuda_bf16.h>
#include <cstdint>
#include <math.h>

// Problem constants
#define BB 8
#define SS 2048
#define DD 1024
#define MTOT (BB * SS)   // 16384

// Scratch (device globals; no allocation allowed)
__device__ float g_q[(size_t)MTOT * DD];
__device__ float g_k[(size_t)MTOT * DD];
__device__ float g_v[(size_t)MTOT * DD];
__device__ float g_s[(size_t)BB * SS * SS];
__device__ float g_x[(size_t)MTOT * DD];

// ---------------------------------------------------------------------------
// PTX helpers: ldmatrix + bf16 mma.sync (family-portable, works on compute_103)
// ---------------------------------------------------------------------------
__device__ __forceinline__ uint32_t smem_u32(const void* p) {
    uint32_t a;
    asm("{ .reg .u64 t; cvta.to.shared.u64 t, %1; cvt.u32.u64 %0, t; }"
        : "=r"(a) : "l"(p));
    return a;
}

#define LDSM4(r0, r1, r2, r3, addr) \
    asm volatile("ldmatrix.sync.aligned.m8n8.x4.shared.b16 {%0,%1,%2,%3}, [%4];" \
                 : "=r"(r0), "=r"(r1), "=r"(r2), "=r"(r3) : "r"(addr))

#define LDSM4T(r0, r1, r2, r3, addr) \
    asm volatile("ldmatrix.sync.aligned.m8n8.x4.trans.shared.b16 {%0,%1,%2,%3}, [%4];" \
                 : "=r"(r0), "=r"(r1), "=r"(r2), "=r"(r3) : "r"(addr))

#define MMA_BF16(d, a, b0, b1)                                              \
    asm volatile(                                                           \
        "mma.sync.aligned.m16n8k16.row.col.f32.bf16.bf16.f32 "              \
        "{%0,%1,%2,%3}, {%4,%5,%6,%7}, {%8,%9}, {%0,%1,%2,%3};"             \
        : "+f"((d)[0]), "+f"((d)[1]), "+f"((d)[2]), "+f"((d)[3])            \
        : "r"((a)[0]), "r"((a)[1]), "r"((a)[2]), "r"((a)[3]),               \
          "r"(b0), "r"(b1))

// fp32 -> bf16 hi/lo split (2-word representation, error <= 2^-17 relative)
__device__ __forceinline__ void split4(float4 v, uint2& hi, uint2& lo) {
    __nv_bfloat162 h01 = __float22bfloat162_rn(make_float2(v.x, v.y));
    __nv_bfloat162 h23 = __float22bfloat162_rn(make_float2(v.z, v.w));
    float2 r01 = make_float2(v.x - __bfloat162float(h01.x),
                             v.y - __bfloat162float(h01.y));
    float2 r23 = make_float2(v.z - __bfloat162float(h23.x),
                             v.w - __bfloat162float(h23.y));
    __nv_bfloat162 l01 = __float22bfloat162_rn(r01);
    __nv_bfloat162 l23 = __float22bfloat162_rn(r23);
    hi = make_uint2(*(uint32_t*)&h01, *(uint32_t*)&h23);
    lo = make_uint2(*(uint32_t*)&l01, *(uint32_t*)&l23);
}

// SMEM tile geometry
#define A_STR   80       // bytes/row: 40 bf16 (32 data + 8 pad) -> conflict-free ldmatrix
#define BNN_STR 272      // bytes/row for NN-B: 136 bf16 (128 data + 8 pad)
#define TILE_A  10240    // 128 rows * 80 B
#define TILE_Bs 10240    // max(128*80, 32*272 = 8704)
#define STAGE_B (2 * TILE_A + 2 * TILE_Bs)   // 40960
#define SMEM_TOT (2 * STAGE_B)               // 81920

// ---------------------------------------------------------------------------
// Split-bf16 tensor-core GEMM: C = alpha * A @ B' (+ bias)
//   BT=true : B is [N][K] row-major (B'[k][n] = B[n][k])  -- proj, QK^T
//   BT=false: B is [K][N] row-major                       -- PV
// CTA tile 128x128, BK=32, 256 threads (8 warps: 2 along m x 4 along n),
// warp tile 64x32. D = Ahi*Bhi + Ahi*Blo + Alo*Bhi, fp32 accumulate.
// ---------------------------------------------------------------------------
template <bool BT, bool BIAS>
__global__ __launch_bounds__(256, 1)
void tc_gemm(const float* __restrict__ A, const float* __restrict__ B,
             const float* __restrict__ bias, float* __restrict__ C,
             int M, int N, int K, float alpha,
             long sA, long sB, long sC)
{
    extern __shared__ char smem[];
    const uint32_t sb = smem_u32(smem);
    const int tid = threadIdx.x;
    const int lane = tid & 31, wid = tid >> 5;
    const int bm = blockIdx.x * 128, bn = blockIdx.y * 128;
    const int wm = (wid & 1) * 64, wn = (wid >> 1) * 32;

    A += (long)blockIdx.z * sA;
    B += (long)blockIdx.z * sB;
    C += (long)blockIdx.z * sC;

    float acc[4][4][4];
#pragma unroll
    for (int i = 0; i < 4; i++)
#pragma unroll
        for (int j = 0; j < 4; j++)
#pragma unroll
            for (int r = 0; r < 4; r++) acc[i][j][r] = 0.f;

    float4 pa[4], pb[4];

    // ---- LDG helpers (fully inlined by unroll) ----
    auto ldgA = [&](int k0) {
#pragma unroll
        for (int it = 0; it < 4; it++) {
            int idx = tid + it * 256;
            int r = idx >> 3, c4 = idx & 7;
            pa[it] = *(const float4*)(A + (long)(bm + r) * K + k0 + c4 * 4);
        }
    };
    auto ldgB = [&](int k0) {
        if (BT) {
#pragma unroll
            for (int it = 0; it < 4; it++) {
                int idx = tid + it * 256;
                int r = idx >> 3, c4 = idx & 7;
                pb[it] = *(const float4*)(B + (long)(bn + r) * K + k0 + c4 * 4);
            }
        } else {
#pragma unroll
            for (int it = 0; it < 4; it++) {
                int idx = tid + it * 256;
                int r = idx >> 5, c4 = idx & 31;
                pb[it] = *(const float4*)(B + (long)(k0 + r) * N + bn + c4 * 4);
            }
        }
    };
    auto stStage = [&](int buf) {
        char* st = smem + buf * STAGE_B;
        char* a_hi = st;
        char* a_lo = st + TILE_A;
        char* b_hi = st + 2 * TILE_A;
        char* b_lo = b_hi + TILE_Bs;
#pragma unroll
        for (int it = 0; it < 4; it++) {
            int idx = tid + it * 256;
            int r = idx >> 3, c4 = idx & 7;
            uint2 hi, lo;
            split4(pa[it], hi, lo);
            int off = r * A_STR + c4 * 8;
            *(uint2*)(a_hi + off) = hi;
            *(uint2*)(a_lo + off) = lo;
        }
        if (BT) {
#pragma unroll
            for (int it = 0; it < 4; it++) {
                int idx = tid + it * 256;
                int r = idx >> 3, c4 = idx & 7;
                uint2 hi, lo;
                split4(pb[it], hi, lo);
                int off = r * A_STR + c4 * 8;
                *(uint2*)(b_hi + off) = hi;
                *(uint2*)(b_lo + off) = lo;
            }
        } else {
#pragma unroll
            for (int it = 0; it < 4; it++) {
                int idx = tid + it * 256;
                int r = idx >> 5, c4 = idx & 31;
                uint2 hi, lo;
                split4(pb[it], hi, lo);
                int off = r * BNN_STR + c4 * 8;
                *(uint2*)(b_hi + off) = hi;
                *(uint2*)(b_lo + off) = lo;
            }
        }
    };

    const int NCH = K >> 5;   // BK = 32

    ldgA(0); ldgB(0);
    stStage(0);
    __syncthreads();

    for (int ch = 0; ch < NCH; ch++) {
        const int buf = ch & 1;
        if (ch + 1 < NCH) { ldgA((ch + 1) << 5); ldgB((ch + 1) << 5); }

        // ---- compute from smem[buf] ----
        const uint32_t st = sb + buf * STAGE_B;
        const uint32_t a_hi = st;
        const uint32_t a_lo = st + TILE_A;
        const uint32_t b_hi = st + 2 * TILE_A;
        const uint32_t b_lo = b_hi + TILE_Bs;

#pragma unroll
        for (int ks = 0; ks < 2; ks++) {
            const int k16 = ks * 16;
            uint32_t ah[4][4], al[4][4];
            {
                const int ar = wm + (lane & 15);
                const int ac = (k16 + (lane >> 4) * 8) * 2;
#pragma unroll
                for (int i = 0; i < 4; i++) {
                    uint32_t ad = a_hi + (ar + i * 16) * A_STR + ac;
                    LDSM4(ah[i][0], ah[i][1], ah[i][2], ah[i][3], ad);
                    uint32_t ad2 = a_lo + (ar + i * 16) * A_STR + ac;
                    LDSM4(al[i][0], al[i][1], al[i][2], al[i][3], ad2);
                }
            }
            uint32_t bh[2][4], bl[2][4];
            if (BT) {
                const int br = wn + (lane & 7) + (lane >> 4) * 8;
                const int bc = (k16 + ((lane >> 3) & 1) * 8) * 2;
#pragma unroll
                for (int j = 0; j < 2; j++) {
                    uint32_t bd = b_hi + (br + j * 16) * A_STR + bc;
                    LDSM4(bh[j][0], bh[j][1], bh[j][2], bh[j][3], bd);
                    uint32_t bd2 = b_lo + (br + j * 16) * A_STR + bc;
                    LDSM4(bl[j][0], bl[j][1], bl[j][2], bl[j][3], bd2);
                }
            } else {
                const int bk = k16 + (lane & 7) + ((lane >> 3) & 1) * 8;
                const int bcol = (wn + (lane >> 4) * 8) * 2;
#pragma unroll
                for (int j = 0; j < 2; j++) {
                    uint32_t bd = b_hi + bk * BNN_STR + bcol + j * 32;
                    LDSM4T(bh[j][0], bh[j][1], bh[j][2], bh[j][3], bd);
                    uint32_t bd2 = b_lo + bk * BNN_STR + bcol + j * 32;
                    LDSM4T(bl[j][0], bl[j][1], bl[j][2], bl[j][3], bd2);
                }
            }
#pragma unroll
            for (int i = 0; i < 4; i++)
#pragma unroll
                for (int j = 0; j < 2; j++)
#pragma unroll
                    for (int h = 0; h < 2; h++) {
                        float* d = acc[i][j * 2 + h];
                        MMA_BF16(d, ah[i], bh[j][2 * h], bh[j][2 * h + 1]);
                        MMA_BF16(d, ah[i], bl[j][2 * h], bl[j][2 * h + 1]);
                        MMA_BF16(d, al[i], bh[j][2 * h], bh[j][2 * h + 1]);
                    }
        }
        __syncthreads();
        if (ch + 1 < NCH) {
            stStage(buf ^ 1);
            __syncthreads();
        }
    }

    // ---- epilogue ----
#pragma unroll
    for (int i = 0; i < 4; i++) {
        const int m0 = bm + wm + i * 16 + (lane >> 2);
#pragma unroll
        for (int jj = 0; jj < 4; jj++) {
            const int n0 = bn + wn + jj * 8 + (lane & 3) * 2;
            float2 v0, v1;
            v0.x = acc[i][jj][0] * alpha;
            v0.y = acc[i][jj][1] * alpha;
            v1.x = acc[i][jj][2] * alpha;
            v1.y = acc[i][jj][3] * alpha;
            if (BIAS) {
                float bx = bias[n0], by = bias[n0 + 1];
                v0.x += bx; v0.y += by;
                v1.x += bx; v1.y += by;
            }
            *(float2*)(C + (long)m0 * N + n0) = v0;
            *(float2*)(C + (long)(m0 + 8) * N + n0) = v1;
        }
    }
}

// ---------------------------------------------------------------------------
// Row softmax over rows of length SS. One block (256 thr) per row.
// ---------------------------------------------------------------------------
__global__ __launch_bounds__(256)
void softmax_rows(float* __restrict__ s)
{
    float* p = s + (long)blockIdx.x * SS;
    const int tid = threadIdx.x;
    __shared__ float red[256];

    float local[8];
    float mx = -1e30f;
#pragma unroll
    for (int i = 0; i < 8; i++) {
        local[i] = p[tid + i * 256];
        mx = fmaxf(mx, local[i]);
    }
    red[tid] = mx;
    __syncthreads();
#pragma unroll
    for (int o = 128; o > 0; o >>= 1) {
        if (tid < o) red[tid] = fmaxf(red[tid], red[tid + o]);
        __syncthreads();
    }
    mx = red[0];
    __syncthreads();

    float sum = 0.f;
#pragma unroll
    for (int i = 0; i < 8; i++) {
        local[i] = __expf(local[i] - mx);
        sum += local[i];
    }
    red[tid] = sum;
    __syncthreads();
#pragma unroll
    for (int o = 128; o > 0; o >>= 1) {
        if (tid < o) red[tid] += red[tid + o];
        __syncthreads();
    }
    float inv = 1.f / red[0];
#pragma unroll
    for (int i = 0; i < 8; i++)
        p[tid + i * 256] = local[i] * inv;
}

// ---------------------------------------------------------------------------
extern "C" void kernel_launch(void* const* d_in, const int* in_sizes, int n_in,
                              void* d_out, int out_size)
{
    const float* query = (const float*)d_in[0];
    const float* key   = (const float*)d_in[1];
    const float* value = (const float*)d_in[2];
    const float* Wq = (const float*)d_in[3];
    const float* bq = (const float*)d_in[4];
    const float* Wk = (const float*)d_in[5];
    const float* bk = (const float*)d_in[6];
    const float* Wv = (const float*)d_in[7];
    const float* bv = (const float*)d_in[8];
    const float* Wo = (const float*)d_in[9];
    const float* bo = (const float*)d_in[10];
    float* out = (float*)d_out;

    float *q, *k, *v, *s, *x;
    cudaGetSymbolAddress((void**)&q, g_q);
    cudaGetSymbolAddress((void**)&k, g_k);
    cudaGetSymbolAddress((void**)&v, g_v);
    cudaGetSymbolAddress((void**)&s, g_s);
    cudaGetSymbolAddress((void**)&x, g_x);

    static bool attr_done = false;
    if (!attr_done) {
        cudaFuncSetAttribute(tc_gemm<true, true>,
                             cudaFuncAttributeMaxDynamicSharedMemorySize, SMEM_TOT);
        cudaFuncSetAttribute(tc_gemm<true, false>,
                             cudaFuncAttributeMaxDynamicSharedMemorySize, SMEM_TOT);
        cudaFuncSetAttribute(tc_gemm<false, false>,
                             cudaFuncAttributeMaxDynamicSharedMemorySize, SMEM_TOT);
        attr_done = true;
    }

    const dim3 blk(256);

    // Projections: [16384,1024] = X @ W^T + b   (NT, bias)
    dim3 gp(MTOT / 128, DD / 128, 1);
    tc_gemm<true, true><<<gp, blk, SMEM_TOT>>>(query, Wq, bq, q, MTOT, DD, DD, 1.f, 0, 0, 0);
    tc_gemm<true, true><<<gp, blk, SMEM_TOT>>>(key,   Wk, bk, k, MTOT, DD, DD, 1.f, 0, 0, 0);
    tc_gemm<true, true><<<gp, blk, SMEM_TOT>>>(value, Wv, bv, v, MTOT, DD, DD, 1.f, 0, 0, 0);

    // Scores: per batch, S = (Q K^T) / sqrt(128)   (NT, batched)
    const float alpha = 0.088388347648318447f;   // 1/sqrt(128)
    dim3 gs(SS / 128, SS / 128, BB);
    tc_gemm<true, false><<<gs, blk, SMEM_TOT>>>(q, k, nullptr, s, SS, SS, DD, alpha,
                                                (long)SS * DD, (long)SS * DD, (long)SS * SS);

    // Softmax over rows
    softmax_rows<<<BB * SS, blk>>>(s);

    // X = P V   (NN, batched)
    dim3 gx(SS / 128, DD / 128, BB);
    tc_gemm<false, false><<<gx, blk, SMEM_TOT>>>(s, v, nullptr, x, SS, DD, SS, 1.f,
                                                 (long)SS * SS, (long)SS * DD, (long)SS * DD);

    // Output projection -> d_out
    tc_gemm<true, true><<<gp, blk, SMEM_TOT>>>(x, Wo, bo, out, MTOT, DD, DD, 1.f, 0, 0, 0);
}